// round 16
// baseline (speedup 1.0000x reference)
#include <cuda_runtime.h>
#include <cstdint>

namespace {
constexpr int P = 32, Cin = 9, H = 64, OUTC = 128, Q = 4;
constexpr int XS = 68;    // X row stride (floats); ≡4 mod 32 -> conflict-free LDS.64
constexpr int WSK = 68;   // W (transposed [n][k]) row stride
constexpr float EPS = 1e-5f;
constexpr int O_X    = 0;               // X[128][XS]
constexpr int O_W    = 128 * XS;        // Wn[64][WSK]
constexpr int O_SC   = O_W + 64 * WSK;  // scales [3][64]
constexpr int O_SH   = O_SC + 192;      // shifts [3][64]
constexpr int O_MK   = O_SH + 192;      // mask [4][32]
constexpr int O_PL   = O_MK + 128;      // pooled[4][64]
constexpr int O_PC   = O_PL + 256;      // pctr [4][64]
constexpr int O_FT   = O_PC + 256;      // feat4[64]
constexpr int O_HD   = O_FT + 256;      // hid4 [64]
constexpr int O_MISC = O_HD + 256;      // valid[4], mode
constexpr int SMEM_BYTES = (O_MISC + 8) * 4;
}

using ull = unsigned long long;

__device__ __forceinline__ uint32_t tf32r(float x) {
  uint32_t u; asm("cvt.rna.tf32.f32 %0, %1;" : "=r"(u) : "f"(x)); return u;
}
// k-group permutation: logical j (0..7) -> physical ((j&3)*2 | j>>2); pairs (j, j+4) adjacent
__device__ __forceinline__ int pc8(int j) { return ((j & 3) << 1) | (j >> 2); }

__device__ __forceinline__ void mma8(float* c, uint32_t a0, uint32_t a1,
                                     uint32_t a2, uint32_t a3,
                                     uint32_t b0, uint32_t b1) {
  asm volatile("mma.sync.aligned.m16n8k8.row.col.f32.tf32.tf32.f32 "
    "{%0,%1,%2,%3}, {%4,%5,%6,%7}, {%8,%9}, {%0,%1,%2,%3};"
    : "+f"(c[0]), "+f"(c[1]), "+f"(c[2]), "+f"(c[3])
    : "r"(a0), "r"(a1), "r"(a2), "r"(a3), "r"(b0), "r"(b1));
}
__device__ __forceinline__ ull fma2(ull a, ull b, ull c) {
  ull d; asm("fma.rn.f32x2 %0, %1, %2, %3;" : "=l"(d) : "l"(a), "l"(b), "l"(c));
  return d;
}
__device__ __forceinline__ ull dup2(float x) {
  ull d; unsigned u = __float_as_uint(x);
  asm("mov.b64 %0, {%1, %1};" : "=l"(d) : "r"(u)); return d;
}
__device__ __forceinline__ float2 unpk(ull v) {
  unsigned a, b; asm("mov.b64 {%0, %1}, %2;" : "=r"(a), "=r"(b) : "l"(v));
  return make_float2(__uint_as_float(a), __uint_as_float(b));
}

// one k-tile: 4 LDS.64 (A) + 8 LDS.64 (B) + 16 HMMA
#define GEMM_KT(kt)                                                           \
  {                                                                           \
    const int kb = 8 * (kt) + 2 * t4;                                         \
    uint2 alo0 = *(const uint2*)(Xs + (32 * w + g) * XS + kb);                \
    uint2 ahi0 = *(const uint2*)(Xs + (32 * w + 8 + g) * XS + kb);            \
    uint2 alo1 = *(const uint2*)(Xs + (32 * w + 16 + g) * XS + kb);           \
    uint2 ahi1 = *(const uint2*)(Xs + (32 * w + 24 + g) * XS + kb);           \
    _Pragma("unroll")                                                         \
    for (int nt = 0; nt < 8; nt++) {                                          \
      uint2 bp = *(const uint2*)(Wn + (8 * nt + g) * WSK + kb);               \
      mma8(acc[0][nt], alo0.x, ahi0.x, alo0.y, ahi0.y, bp.x, bp.y);           \
      mma8(acc[1][nt], alo1.x, ahi1.x, alo1.y, ahi1.y, bp.x, bp.y);           \
    }                                                                         \
  }

__global__ void __launch_bounds__(128, 3)
pnet_tc(const float* __restrict__ poly, const void* __restrict__ mask,
        const float* __restrict__ pre_w, const float* __restrict__ pre_b,
        const float* __restrict__ pre_g, const float* __restrict__ pre_be,
        const float* __restrict__ pre_rm, const float* __restrict__ pre_rv,
        const float* __restrict__ m1_w, const float* __restrict__ m1_b,
        const float* __restrict__ m1_g, const float* __restrict__ m1_be,
        const float* __restrict__ m1_rm, const float* __restrict__ m1_rv,
        const float* __restrict__ m2_w, const float* __restrict__ m2_b,
        const float* __restrict__ m2_g, const float* __restrict__ m2_be,
        const float* __restrict__ m2_rm, const float* __restrict__ m2_rv,
        const float* __restrict__ o1_w, const float* __restrict__ o1_b,
        const float* __restrict__ o2_w, const float* __restrict__ o2_b,
        float* __restrict__ out, int n_poly)
{
  extern __shared__ __align__(16) float S[];
  float*  Xs     = S + O_X;
  float*  Wn     = S + O_W;
  float*  sc     = S + O_SC;
  float*  sh     = S + O_SH;
  float*  mk     = S + O_MK;
  float*  pooled = S + O_PL;
  float*  pctr   = S + O_PC;
  float4* feat4  = (float4*)(S + O_FT);
  float4* hid4   = (float4*)(S + O_HD);
  int*    misc   = (int*)(S + O_MISC);

  const int tid = threadIdx.x, w = tid >> 5, lane = tid & 31;
  const int g = lane >> 2, t4 = lane & 3;
  const int j0 = pc8(2 * t4), j1 = pc8(2 * t4 + 1);   // permuted n-offsets for epilogue
  const int pbase = blockIdx.x * Q;
  const bool okq = (pbase + w) < n_poly;

  if (tid == 0) {
    const unsigned* w32 = (const unsigned*)mask;
    bool big = false, allf = true;
    #pragma unroll
    for (int i = 0; i < 32; i++) {
      unsigned v = w32[i];
      big |= (v > 1u); allf &= (v == 0u || v == 0x3f800000u);
    }
    misc[4] = big ? (allf ? 1 : 2) : 0;
  }
  if (tid < 64) {
    int c = tid;
    float s0 = pre_g[c] * rsqrtf(pre_rv[c] + EPS);
    sc[c] = s0;       sh[c]       = (pre_b[c] - pre_rm[c]) * s0 + pre_be[c];
    float s1 = m1_g[c] * rsqrtf(m1_rv[c] + EPS);
    sc[64 + c] = s1;  sh[64 + c]  = (m1_b[c] - m1_rm[c]) * s1 + m1_be[c];
    float s2 = m2_g[c] * rsqrtf(m2_rv[c] + EPS);
    sc[128 + c] = s2; sh[128 + c] = (m2_b[c] - m2_rm[c]) * s2 + m2_be[c];
  }
  __syncthreads();
  const int mode = misc[4];

  // ---- mask (warp = polyline, lane = point) ----
  {
    long long gi = (long long)(pbase + w) * P + lane;
    float mv = 0.f;
    if (okq) {
      if (mode == 2)      mv = ((const unsigned char*)mask)[gi] ? 1.f : 0.f;
      else if (mode == 1) mv = (((const float*)mask)[gi] != 0.f) ? 1.f : 0.f;
      else                mv = ((const int*)mask)[gi] ? 1.f : 0.f;
    }
    mk[w * 32 + lane] = mv;
    unsigned bal = __ballot_sync(0xffffffffu, mv != 0.f);
    if (lane == 0) misc[w] = (bal != 0u) ? 1 : 0;
  }

  // ---- stage W_pre transposed+permuted: Wn[n][pk], k<16 zero-padded ----
  for (int i = tid; i < 16 * 16; i += 128) {
    int k = i >> 4, n4 = (i & 15) * 4;
    int pk = (k & ~7) + pc8(k & 7);
    #pragma unroll
    for (int j = 0; j < 4; j++) {
      float v = (k < Cin) ? __ldg(&pre_w[k * H + n4 + j]) * sc[n4 + j] : 0.f;
      ((uint32_t*)Wn)[(n4 + j) * WSK + pk] = tf32r(v);
    }
  }
  // ---- stage X_pre: thread = row, cols 0..15 permuted ----
  {
    int q = tid >> 5, p = tid & 31;
    const float* prow = poly + ((long long)(pbase + q) * P + p) * Cin;
    bool ok = (pbase + q) < n_poly;
    uint32_t* xr = (uint32_t*)Xs + tid * XS;
    #pragma unroll
    for (int c = 0; c < 16; c++) {
      float x = (ok && c < Cin) ? __ldg(&prow[c]) : 0.f;
      xr[(c & ~7) + pc8(c & 7)] = tf32r(x);
    }
  }
  __syncthreads();

  float acc[2][8][4];

  // ================= GEMM1: X[128x16] @ Wpre =================
  #pragma unroll
  for (int mt = 0; mt < 2; mt++)
    #pragma unroll
    for (int nt = 0; nt < 8; nt++)
      #pragma unroll
      for (int j = 0; j < 4; j++) acc[mt][nt][j] = 0.f;
  GEMM_KT(0) GEMM_KT(1)
  __syncthreads();

  // epilogue1: relu(c+sh)*mask -> X (tf32, permuted cols); stage W_m1 lower
  #pragma unroll
  for (int mt = 0; mt < 2; mt++) {
    int r0 = 32 * w + 16 * mt + g;
    float mv0 = mk[w * 32 + 16 * mt + g], mv1 = mk[w * 32 + 16 * mt + g + 8];
    #pragma unroll
    for (int nt = 0; nt < 8; nt++) {
      int n0 = 8 * nt + 2 * t4;
      float s00 = sh[n0], s01 = sh[n0 + 1];
      uint32_t* xr0 = (uint32_t*)Xs + r0 * XS + 8 * nt;
      uint32_t* xr1 = (uint32_t*)Xs + (r0 + 8) * XS + 8 * nt;
      xr0[j0] = tf32r(fmaxf(acc[mt][nt][0] + s00, 0.f) * mv0);
      xr0[j1] = tf32r(fmaxf(acc[mt][nt][1] + s01, 0.f) * mv0);
      xr1[j0] = tf32r(fmaxf(acc[mt][nt][2] + s00, 0.f) * mv1);
      xr1[j1] = tf32r(fmaxf(acc[mt][nt][3] + s01, 0.f) * mv1);
    }
  }
  for (int i = tid; i < 64 * 16; i += 128) {
    int k = i >> 4, n4 = (i & 15) * 4;
    int pk = (k & ~7) + pc8(k & 7);
    float4 v = __ldg((const float4*)&m1_w[k * H + n4]);
    ((uint32_t*)Wn)[(n4 + 0) * WSK + pk] = tf32r(v.x * sc[64 + n4 + 0]);
    ((uint32_t*)Wn)[(n4 + 1) * WSK + pk] = tf32r(v.y * sc[64 + n4 + 1]);
    ((uint32_t*)Wn)[(n4 + 2) * WSK + pk] = tf32r(v.z * sc[64 + n4 + 2]);
    ((uint32_t*)Wn)[(n4 + 3) * WSK + pk] = tf32r(v.w * sc[64 + n4 + 3]);
  }
  __syncthreads();

  // ===== pooled[w][ch] over points (permuted col read) =====
  #pragma unroll
  for (int half = 0; half < 2; half++) {
    int ch = lane + 32 * half;
    int phys = (ch & ~7) + pc8(ch & 7);
    float m = 0.f;
    #pragma unroll 8
    for (int p = 0; p < 32; p++) m = fmaxf(m, Xs[(32 * w + p) * XS + phys]);
    pooled[w * 64 + ch] = m;
  }
  __syncthreads();

  // ===== pctr = (pooled @ m1_w_upper) * scale_m1 =====
  {
    int pair = tid >> 6, ch = tid & 63;
    float a0 = 0.f, a1 = 0.f;
    #pragma unroll 8
    for (int k = 0; k < 64; k++) {
      float wv = __ldg(&m1_w[(H + k) * H + ch]);
      a0 = fmaf(pooled[(2 * pair) * 64 + k], wv, a0);
      a1 = fmaf(pooled[(2 * pair + 1) * 64 + k], wv, a1);
    }
    float s = sc[64 + ch];
    pctr[(2 * pair) * 64 + ch]     = a0 * s;
    pctr[(2 * pair + 1) * 64 + ch] = a1 * s;
  }
  __syncthreads();

  // ================= GEMM2: X @ Wm1 =================
  #pragma unroll
  for (int mt = 0; mt < 2; mt++)
    #pragma unroll
    for (int nt = 0; nt < 8; nt++)
      #pragma unroll
      for (int j = 0; j < 4; j++) acc[mt][nt][j] = 0.f;
  #pragma unroll
  for (int kt = 0; kt < 8; kt++) GEMM_KT(kt)
  __syncthreads();

  // epilogue2: relu(c+pctr+sh_m1) -> X (tf32, permuted); stage W_m2
  #pragma unroll
  for (int mt = 0; mt < 2; mt++) {
    int r0 = 32 * w + 16 * mt + g;
    #pragma unroll
    for (int nt = 0; nt < 8; nt++) {
      int n0 = 8 * nt + 2 * t4;
      float c00 = pctr[w * 64 + n0] + sh[64 + n0];
      float c01 = pctr[w * 64 + n0 + 1] + sh[64 + n0 + 1];
      uint32_t* xr0 = (uint32_t*)Xs + r0 * XS + 8 * nt;
      uint32_t* xr1 = (uint32_t*)Xs + (r0 + 8) * XS + 8 * nt;
      xr0[j0] = tf32r(fmaxf(acc[mt][nt][0] + c00, 0.f));
      xr0[j1] = tf32r(fmaxf(acc[mt][nt][1] + c01, 0.f));
      xr1[j0] = tf32r(fmaxf(acc[mt][nt][2] + c00, 0.f));
      xr1[j1] = tf32r(fmaxf(acc[mt][nt][3] + c01, 0.f));
    }
  }
  for (int i = tid; i < 64 * 16; i += 128) {
    int k = i >> 4, n4 = (i & 15) * 4;
    int pk = (k & ~7) + pc8(k & 7);
    float4 v = __ldg((const float4*)&m2_w[k * H + n4]);
    ((uint32_t*)Wn)[(n4 + 0) * WSK + pk] = tf32r(v.x * sc[128 + n4 + 0]);
    ((uint32_t*)Wn)[(n4 + 1) * WSK + pk] = tf32r(v.y * sc[128 + n4 + 1]);
    ((uint32_t*)Wn)[(n4 + 2) * WSK + pk] = tf32r(v.z * sc[128 + n4 + 2]);
    ((uint32_t*)Wn)[(n4 + 3) * WSK + pk] = tf32r(v.w * sc[128 + n4 + 3]);
  }
  __syncthreads();

  // ================= GEMM3: X @ Wm2 =================
  #pragma unroll
  for (int mt = 0; mt < 2; mt++)
    #pragma unroll
    for (int nt = 0; nt < 8; nt++)
      #pragma unroll
      for (int j = 0; j < 4; j++) acc[mt][nt][j] = 0.f;
  #pragma unroll
  for (int kt = 0; kt < 8; kt++) GEMM_KT(kt)
  __syncthreads();

  // epilogue3: relu(c+sh_m2)*mask -> X (fp32, TRUE cols; feeds pooling only)
  #pragma unroll
  for (int mt = 0; mt < 2; mt++) {
    int r0 = 32 * w + 16 * mt + g;
    float mv0 = mk[w * 32 + 16 * mt + g], mv1 = mk[w * 32 + 16 * mt + g + 8];
    #pragma unroll
    for (int nt = 0; nt < 8; nt++) {
      int n0 = 8 * nt + 2 * t4;
      float s00 = sh[128 + n0], s01 = sh[128 + n0 + 1];
      float* xr0 = Xs + r0 * XS + n0;
      float* xr1 = Xs + (r0 + 8) * XS + n0;
      xr0[0] = fmaxf(acc[mt][nt][0] + s00, 0.f) * mv0;
      xr0[1] = fmaxf(acc[mt][nt][1] + s01, 0.f) * mv0;
      xr1[0] = fmaxf(acc[mt][nt][2] + s00, 0.f) * mv1;
      xr1[1] = fmaxf(acc[mt][nt][3] + s01, 0.f) * mv1;
    }
  }
  __syncthreads();

  // ===== feat pooling -> feat4[ch] interleaved {q0..q3} =====
  #pragma unroll
  for (int half = 0; half < 2; half++) {
    int ch = lane + 32 * half;
    float m = 0.f;
    #pragma unroll 8
    for (int p = 0; p < 32; p++) m = fmaxf(m, Xs[(32 * w + p) * XS + ch]);
    ((float*)&feat4[ch])[w] = m;
  }
  __syncthreads();

  // ===== head o1: hid = relu(feat @ o1_w + o1_b) =====
  {
    int pair = tid >> 6, ch = tid & 63;
    ull a = 0ull;
    #pragma unroll 8
    for (int k = 0; k < 64; k++) {
      float wv = __ldg(&o1_w[k * H + ch]);
      a = fma2(*(const ull*)((const float*)&feat4[k] + 2 * pair), dup2(wv), a);
    }
    float bia = __ldg(&o1_b[ch]);
    float2 r = unpk(a);
    ((float*)&hid4[ch])[2 * pair]     = fmaxf(r.x + bia, 0.f);
    ((float*)&hid4[ch])[2 * pair + 1] = fmaxf(r.y + bia, 0.f);
  }
  __syncthreads();

  // ===== head o2: out = hid @ o2_w + o2_b =====
  {
    float vf0 = misc[0] ? 1.f : 0.f, vf1 = misc[1] ? 1.f : 0.f;
    float vf2 = misc[2] ? 1.f : 0.f, vf3 = misc[3] ? 1.f : 0.f;
    ull a01 = dup2(__ldg(&o2_b[tid])), a23 = a01;
    #pragma unroll 8
    for (int k = 0; k < 64; k++) {
      float wv = __ldg(&o2_w[k * OUTC + tid]);
      ull wd = dup2(wv);
      const ull* hp = (const ull*)&hid4[k];
      a01 = fma2(hp[0], wd, a01);
      a23 = fma2(hp[1], wd, a23);
    }
    float2 r01 = unpk(a01), r23 = unpk(a23);
    long long ob = (long long)pbase * OUTC + tid;
    if (pbase + 0 < n_poly) out[ob]            = r01.x * vf0;
    if (pbase + 1 < n_poly) out[ob + OUTC]     = r01.y * vf1;
    if (pbase + 2 < n_poly) out[ob + 2 * OUTC] = r23.x * vf2;
    if (pbase + 3 < n_poly) out[ob + 3 * OUTC] = r23.y * vf3;
  }
}

extern "C" void kernel_launch(void* const* d_in, const int* in_sizes, int n_in,
                              void* d_out, int out_size)
{
  (void)in_sizes; (void)n_in;
  const int n_poly = out_size / OUTC;   // 16384
  const int nblk = (n_poly + Q - 1) / Q;
  cudaFuncSetAttribute(pnet_tc, cudaFuncAttributeMaxDynamicSharedMemorySize, SMEM_BYTES);
  pnet_tc<<<nblk, 128, SMEM_BYTES>>>(
      (const float*)d_in[0],  d_in[1],
      (const float*)d_in[2],  (const float*)d_in[3],
      (const float*)d_in[4],  (const float*)d_in[5],
      (const float*)d_in[6],  (const float*)d_in[7],
      (const float*)d_in[8],  (const float*)d_in[9],
      (const float*)d_in[10], (const float*)d_in[11],
      (const float*)d_in[12], (const float*)d_in[13],
      (const float*)d_in[14], (const float*)d_in[15],
      (const float*)d_in[16], (const float*)d_in[17],
      (const float*)d_in[18], (const float*)d_in[19],
      (const float*)d_in[20], (const float*)d_in[21],
      (const float*)d_in[22], (const float*)d_in[23],
      (float*)d_out, n_poly);
}

// round 17
// speedup vs baseline: 1.1483x; 1.1483x over previous
#include <cuda_runtime.h>
#include <cstdint>

namespace {
constexpr int P = 32, Cin = 9, H = 64, OUTC = 128, Q = 4;
constexpr int XS = 68;   // X row stride (floats): conflict-free A-fragment loads
constexpr int WS = 72;   // W row stride (floats): conflict-free B-fragment loads
constexpr float EPS = 1e-5f;
// smem layout (float offsets). feat4/hid4 OVERLAY the W region (W dead after GEMM3).
constexpr int O_X    = 0;                 // X[128][XS]            8704 floats
constexpr int O_W    = 128 * XS;          // W[64][WS]             4608 floats
constexpr int O_FT   = O_W;               // feat4[64] (overlay)    256 floats
constexpr int O_HD   = O_W + 256;         // hid4 [64] (overlay)    256 floats
constexpr int O_SC   = O_W + 64 * WS;     // scales [3][64]
constexpr int O_SH   = O_SC + 192;        // shifts [3][64]
constexpr int O_MK   = O_SH + 192;        // mask  [4][32]
constexpr int O_PL   = O_MK + 128;        // pooled[4][64]
constexpr int O_PC   = O_PL + 256;        // pctr  [4][64]
constexpr int O_MISC = O_PC + 256;        // valid[4], mode
constexpr int SMEM_BYTES = (O_MISC + 8) * 4;   // 57376 B -> 4 CTAs/SM
}

using ull = unsigned long long;

__device__ __forceinline__ uint32_t tf32r(float x) {
  uint32_t u; asm("cvt.rna.tf32.f32 %0, %1;" : "=r"(u) : "f"(x)); return u;
}
__device__ __forceinline__ void mma8(float* c, const uint32_t* a, uint32_t b0, uint32_t b1) {
  asm volatile("mma.sync.aligned.m16n8k8.row.col.f32.tf32.tf32.f32 "
    "{%0,%1,%2,%3}, {%4,%5,%6,%7}, {%8,%9}, {%0,%1,%2,%3};"
    : "+f"(c[0]), "+f"(c[1]), "+f"(c[2]), "+f"(c[3])
    : "r"(a[0]), "r"(a[1]), "r"(a[2]), "r"(a[3]), "r"(b0), "r"(b1));
}
__device__ __forceinline__ ull fma2(ull a, ull b, ull c) {
  ull d; asm("fma.rn.f32x2 %0, %1, %2, %3;" : "=l"(d) : "l"(a), "l"(b), "l"(c));
  return d;
}
__device__ __forceinline__ ull dup2(float x) {
  ull d; unsigned u = __float_as_uint(x);
  asm("mov.b64 %0, {%1, %1};" : "=l"(d) : "r"(u)); return d;
}
__device__ __forceinline__ float2 unpk(ull v) {
  unsigned a, b; asm("mov.b64 {%0, %1}, %2;" : "=r"(a), "=r"(b) : "l"(v));
  return make_float2(__uint_as_float(a), __uint_as_float(b));
}

__global__ void __launch_bounds__(128)
pnet_tc(const float* __restrict__ poly, const void* __restrict__ mask,
        const float* __restrict__ pre_w, const float* __restrict__ pre_b,
        const float* __restrict__ pre_g, const float* __restrict__ pre_be,
        const float* __restrict__ pre_rm, const float* __restrict__ pre_rv,
        const float* __restrict__ m1_w, const float* __restrict__ m1_b,
        const float* __restrict__ m1_g, const float* __restrict__ m1_be,
        const float* __restrict__ m1_rm, const float* __restrict__ m1_rv,
        const float* __restrict__ m2_w, const float* __restrict__ m2_b,
        const float* __restrict__ m2_g, const float* __restrict__ m2_be,
        const float* __restrict__ m2_rm, const float* __restrict__ m2_rv,
        const float* __restrict__ o1_w, const float* __restrict__ o1_b,
        const float* __restrict__ o2_w, const float* __restrict__ o2_b,
        float* __restrict__ out, int n_poly)
{
  extern __shared__ __align__(16) float S[];
  float*  Xs     = S + O_X;
  float*  Wsm    = S + O_W;
  float*  sc     = S + O_SC;
  float*  sh     = S + O_SH;
  float*  mk     = S + O_MK;
  float*  pooled = S + O_PL;
  float*  pctr   = S + O_PC;
  float4* feat4  = (float4*)(S + O_FT);   // overlays W (dead after GEMM3)
  float4* hid4   = (float4*)(S + O_HD);   // overlays W
  int*    misc   = (int*)(S + O_MISC);

  const int tid = threadIdx.x, w = tid >> 5, lane = tid & 31;
  const int g = lane >> 2, t4 = lane & 3;
  const int pbase = blockIdx.x * Q;
  const bool okq = (pbase + w) < n_poly;

  // ---- mask dtype detection ----
  if (tid == 0) {
    const unsigned* w32 = (const unsigned*)mask;
    bool big = false, allf = true;
    #pragma unroll
    for (int i = 0; i < 32; i++) {
      unsigned v = w32[i];
      big |= (v > 1u); allf &= (v == 0u || v == 0x3f800000u);
    }
    misc[4] = big ? (allf ? 1 : 2) : 0;
  }
  // BN scales + shifts
  if (tid < 64) {
    int c = tid;
    float s0 = pre_g[c] * rsqrtf(pre_rv[c] + EPS);
    sc[c] = s0;       sh[c]       = (pre_b[c] - pre_rm[c]) * s0 + pre_be[c];
    float s1 = m1_g[c] * rsqrtf(m1_rv[c] + EPS);
    sc[64 + c] = s1;  sh[64 + c]  = (m1_b[c] - m1_rm[c]) * s1 + m1_be[c];
    float s2 = m2_g[c] * rsqrtf(m2_rv[c] + EPS);
    sc[128 + c] = s2; sh[128 + c] = (m2_b[c] - m2_rm[c]) * s2 + m2_be[c];
  }
  __syncthreads();
  const int mode = misc[4];

  // ---- mask (warp = polyline, lane = point) ----
  {
    long long gi = (long long)(pbase + w) * P + lane;
    float mv = 0.f;
    if (okq) {
      if (mode == 2)      mv = ((const unsigned char*)mask)[gi] ? 1.f : 0.f;
      else if (mode == 1) mv = (((const float*)mask)[gi] != 0.f) ? 1.f : 0.f;
      else                mv = ((const int*)mask)[gi] ? 1.f : 0.f;
    }
    mk[w * 32 + lane] = mv;
    unsigned bal = __ballot_sync(0xffffffffu, mv != 0.f);
    if (lane == 0) misc[w] = (bal != 0u) ? 1 : 0;
  }

  // ---- stage W_pre (16x64, zero-padded K, scale-folded, tf32) ----
  for (int i = tid; i < 16 * 64; i += 128) {
    int k = i >> 6, n = i & 63;
    float v = (k < Cin) ? __ldg(&pre_w[k * H + n]) * sc[n] : 0.f;
    ((uint32_t*)Wsm)[k * WS + n] = tf32r(v);
  }
  // ---- stage X_pre: thread t = row (point), cols 0..15 ----
  {
    int q = tid >> 5, p = tid & 31;
    const float* prow = poly + ((long long)(pbase + q) * P + p) * Cin;
    bool ok = (pbase + q) < n_poly;
    uint32_t* xr = (uint32_t*)Xs + tid * XS;
    #pragma unroll
    for (int c = 0; c < 16; c++) {
      float x = (ok && c < Cin) ? __ldg(&prow[c]) : 0.f;
      xr[c] = tf32r(x);
    }
  }
  __syncthreads();

  float acc[2][8][4];

  // ================= GEMM1: X[128x16] @ Wpre[16x64] =================
  #pragma unroll
  for (int mt = 0; mt < 2; mt++)
    #pragma unroll
    for (int nt = 0; nt < 8; nt++)
      #pragma unroll
      for (int j = 0; j < 4; j++) acc[mt][nt][j] = 0.f;

  #pragma unroll
  for (int kt = 0; kt < 2; kt++) {
    uint32_t A[2][4];
    #pragma unroll
    for (int mt = 0; mt < 2; mt++) {
      const uint32_t* xb = (const uint32_t*)Xs + (32 * w + 16 * mt) * XS + 8 * kt;
      A[mt][0] = xb[g * XS + t4];        A[mt][1] = xb[(g + 8) * XS + t4];
      A[mt][2] = xb[g * XS + t4 + 4];    A[mt][3] = xb[(g + 8) * XS + t4 + 4];
    }
    #pragma unroll
    for (int nt = 0; nt < 8; nt++) {
      const uint32_t* wb = (const uint32_t*)Wsm + (8 * kt) * WS + 8 * nt;
      uint32_t b0 = wb[t4 * WS + g], b1 = wb[(t4 + 4) * WS + g];
      mma8(acc[0][nt], A[0], b0, b1);
      mma8(acc[1][nt], A[1], b0, b1);
    }
  }
  __syncthreads();   // all X/W reads done

  // epilogue1: relu(c+sh)*mask -> X (tf32); stage W_m1 lower
  #pragma unroll
  for (int mt = 0; mt < 2; mt++) {
    int r0 = 32 * w + 16 * mt + g;
    float mv0 = mk[w * 32 + 16 * mt + g], mv1 = mk[w * 32 + 16 * mt + g + 8];
    #pragma unroll
    for (int nt = 0; nt < 8; nt++) {
      int n0 = 8 * nt + 2 * t4;
      float s00 = sh[n0], s01 = sh[n0 + 1];
      uint32_t* xr0 = (uint32_t*)Xs + r0 * XS + n0;
      uint32_t* xr1 = (uint32_t*)Xs + (r0 + 8) * XS + n0;
      xr0[0] = tf32r(fmaxf(acc[mt][nt][0] + s00, 0.f) * mv0);
      xr0[1] = tf32r(fmaxf(acc[mt][nt][1] + s01, 0.f) * mv0);
      xr1[0] = tf32r(fmaxf(acc[mt][nt][2] + s00, 0.f) * mv1);
      xr1[1] = tf32r(fmaxf(acc[mt][nt][3] + s01, 0.f) * mv1);
    }
  }
  for (int i = tid; i < 64 * 64; i += 128) {
    int k = i >> 6, n = i & 63;
    ((uint32_t*)Wsm)[k * WS + n] = tf32r(__ldg(&m1_w[k * H + n]) * sc[64 + n]);
  }
  __syncthreads();

  // ===== pooled[w][ch] = max over this polyline's points =====
  #pragma unroll
  for (int half = 0; half < 2; half++) {
    int ch = lane + 32 * half;
    float m = 0.f;
    #pragma unroll 8
    for (int p = 0; p < 32; p++) m = fmaxf(m, Xs[(32 * w + p) * XS + ch]);
    pooled[w * 64 + ch] = m;
  }
  __syncthreads();

  // ===== pctr = (pooled @ m1_w_upper) * scale_m1 (fp32) =====
  {
    int pair = tid >> 6, ch = tid & 63;
    float a0 = 0.f, a1 = 0.f;
    #pragma unroll 8
    for (int k = 0; k < 64; k++) {
      float wv = __ldg(&m1_w[(H + k) * H + ch]);
      a0 = fmaf(pooled[(2 * pair) * 64 + k], wv, a0);
      a1 = fmaf(pooled[(2 * pair + 1) * 64 + k], wv, a1);
    }
    float s = sc[64 + ch];
    pctr[(2 * pair) * 64 + ch]     = a0 * s;
    pctr[(2 * pair + 1) * 64 + ch] = a1 * s;
  }
  __syncthreads();

  // ================= GEMM2: X[128x64] @ Wm1[64x64] =================
  #pragma unroll
  for (int mt = 0; mt < 2; mt++)
    #pragma unroll
    for (int nt = 0; nt < 8; nt++)
      #pragma unroll
      for (int j = 0; j < 4; j++) acc[mt][nt][j] = 0.f;

  #pragma unroll 4
  for (int kt = 0; kt < 8; kt++) {
    uint32_t A[2][4];
    #pragma unroll
    for (int mt = 0; mt < 2; mt++) {
      const uint32_t* xb = (const uint32_t*)Xs + (32 * w + 16 * mt) * XS + 8 * kt;
      A[mt][0] = xb[g * XS + t4];        A[mt][1] = xb[(g + 8) * XS + t4];
      A[mt][2] = xb[g * XS + t4 + 4];    A[mt][3] = xb[(g + 8) * XS + t4 + 4];
    }
    #pragma unroll
    for (int nt = 0; nt < 8; nt++) {
      const uint32_t* wb = (const uint32_t*)Wsm + (8 * kt) * WS + 8 * nt;
      uint32_t b0 = wb[t4 * WS + g], b1 = wb[(t4 + 4) * WS + g];
      mma8(acc[0][nt], A[0], b0, b1);
      mma8(acc[1][nt], A[1], b0, b1);
    }
  }
  __syncthreads();

  // epilogue2: relu(c+pctr+sh_m1) -> X (tf32); stage W_m2
  #pragma unroll
  for (int mt = 0; mt < 2; mt++) {
    int r0 = 32 * w + 16 * mt + g;
    #pragma unroll
    for (int nt = 0; nt < 8; nt++) {
      int n0 = 8 * nt + 2 * t4;
      float c00 = pctr[w * 64 + n0] + sh[64 + n0];
      float c01 = pctr[w * 64 + n0 + 1] + sh[64 + n0 + 1];
      uint32_t* xr0 = (uint32_t*)Xs + r0 * XS + n0;
      uint32_t* xr1 = (uint32_t*)Xs + (r0 + 8) * XS + n0;
      xr0[0] = tf32r(fmaxf(acc[mt][nt][0] + c00, 0.f));
      xr0[1] = tf32r(fmaxf(acc[mt][nt][1] + c01, 0.f));
      xr1[0] = tf32r(fmaxf(acc[mt][nt][2] + c00, 0.f));
      xr1[1] = tf32r(fmaxf(acc[mt][nt][3] + c01, 0.f));
    }
  }
  for (int i = tid; i < 64 * 64; i += 128) {
    int k = i >> 6, n = i & 63;
    ((uint32_t*)Wsm)[k * WS + n] = tf32r(__ldg(&m2_w[k * H + n]) * sc[128 + n]);
  }
  __syncthreads();

  // ================= GEMM3: X[128x64] @ Wm2[64x64] =================
  #pragma unroll
  for (int mt = 0; mt < 2; mt++)
    #pragma unroll
    for (int nt = 0; nt < 8; nt++)
      #pragma unroll
      for (int j = 0; j < 4; j++) acc[mt][nt][j] = 0.f;

  #pragma unroll 4
  for (int kt = 0; kt < 8; kt++) {
    uint32_t A[2][4];
    #pragma unroll
    for (int mt = 0; mt < 2; mt++) {
      const uint32_t* xb = (const uint32_t*)Xs + (32 * w + 16 * mt) * XS + 8 * kt;
      A[mt][0] = xb[g * XS + t4];        A[mt][1] = xb[(g + 8) * XS + t4];
      A[mt][2] = xb[g * XS + t4 + 4];    A[mt][3] = xb[(g + 8) * XS + t4 + 4];
    }
    #pragma unroll
    for (int nt = 0; nt < 8; nt++) {
      const uint32_t* wb = (const uint32_t*)Wsm + (8 * kt) * WS + 8 * nt;
      uint32_t b0 = wb[t4 * WS + g], b1 = wb[(t4 + 4) * WS + g];
      mma8(acc[0][nt], A[0], b0, b1);
      mma8(acc[1][nt], A[1], b0, b1);
    }
  }
  __syncthreads();   // last W read — feat4/hid4 overlay becomes safe after this

  // epilogue3: relu(c+sh_m2)*mask -> X (fp32, feeds pooling only)
  #pragma unroll
  for (int mt = 0; mt < 2; mt++) {
    int r0 = 32 * w + 16 * mt + g;
    float mv0 = mk[w * 32 + 16 * mt + g], mv1 = mk[w * 32 + 16 * mt + g + 8];
    #pragma unroll
    for (int nt = 0; nt < 8; nt++) {
      int n0 = 8 * nt + 2 * t4;
      float s00 = sh[128 + n0], s01 = sh[128 + n0 + 1];
      float* xr0 = Xs + r0 * XS + n0;
      float* xr1 = Xs + (r0 + 8) * XS + n0;
      xr0[0] = fmaxf(acc[mt][nt][0] + s00, 0.f) * mv0;
      xr0[1] = fmaxf(acc[mt][nt][1] + s01, 0.f) * mv0;
      xr1[0] = fmaxf(acc[mt][nt][2] + s00, 0.f) * mv1;
      xr1[1] = fmaxf(acc[mt][nt][3] + s01, 0.f) * mv1;
    }
  }
  __syncthreads();

  // ===== feat pooling -> feat4[ch] interleaved {q0,q1,q2,q3} =====
  #pragma unroll
  for (int half = 0; half < 2; half++) {
    int ch = lane + 32 * half;
    float m = 0.f;
    #pragma unroll 8
    for (int p = 0; p < 32; p++) m = fmaxf(m, Xs[(32 * w + p) * XS + ch]);
    ((float*)&feat4[ch])[w] = m;
  }
  __syncthreads();

  // ===== head o1: hid = relu(feat @ o1_w + o1_b) =====
  {
    int pair = tid >> 6, ch = tid & 63;
    ull a = 0ull;
    #pragma unroll 8
    for (int k = 0; k < 64; k++) {
      float wv = __ldg(&o1_w[k * H + ch]);
      a = fma2(*(const ull*)((const float*)&feat4[k] + 2 * pair), dup2(wv), a);
    }
    float bia = __ldg(&o1_b[ch]);
    float2 r = unpk(a);
    ((float*)&hid4[ch])[2 * pair]     = fmaxf(r.x + bia, 0.f);
    ((float*)&hid4[ch])[2 * pair + 1] = fmaxf(r.y + bia, 0.f);
  }
  __syncthreads();

  // ===== head o2: out = hid @ o2_w + o2_b =====
  {
    float vf0 = misc[0] ? 1.f : 0.f, vf1 = misc[1] ? 1.f : 0.f;
    float vf2 = misc[2] ? 1.f : 0.f, vf3 = misc[3] ? 1.f : 0.f;
    ull a01 = dup2(__ldg(&o2_b[tid])), a23 = a01;
    #pragma unroll 8
    for (int k = 0; k < 64; k++) {
      float wv = __ldg(&o2_w[k * OUTC + tid]);
      ull wd = dup2(wv);
      const ull* hp = (const ull*)&hid4[k];
      a01 = fma2(hp[0], wd, a01);
      a23 = fma2(hp[1], wd, a23);
    }
    float2 r01 = unpk(a01), r23 = unpk(a23);
    long long ob = (long long)pbase * OUTC + tid;
    if (pbase + 0 < n_poly) out[ob]            = r01.x * vf0;
    if (pbase + 1 < n_poly) out[ob + OUTC]     = r01.y * vf1;
    if (pbase + 2 < n_poly) out[ob + 2 * OUTC] = r23.x * vf2;
    if (pbase + 3 < n_poly) out[ob + 3 * OUTC] = r23.y * vf3;
  }
}

extern "C" void kernel_launch(void* const* d_in, const int* in_sizes, int n_in,
                              void* d_out, int out_size)
{
  (void)in_sizes; (void)n_in;
  const int n_poly = out_size / OUTC;   // 16384
  const int nblk = (n_poly + Q - 1) / Q;
  cudaFuncSetAttribute(pnet_tc, cudaFuncAttributeMaxDynamicSharedMemorySize, SMEM_BYTES);
  pnet_tc<<<nblk, 128, SMEM_BYTES>>>(
      (const float*)d_in[0],  d_in[1],
      (const float*)d_in[2],  (const float*)d_in[3],
      (const float*)d_in[4],  (const float*)d_in[5],
      (const float*)d_in[6],  (const float*)d_in[7],
      (const float*)d_in[8],  (const float*)d_in[9],
      (const float*)d_in[10], (const float*)d_in[11],
      (const float*)d_in[12], (const float*)d_in[13],
      (const float*)d_in[14], (const float*)d_in[15],
      (const float*)d_in[16], (const float*)d_in[17],
      (const float*)d_in[18], (const float*)d_in[19],
      (const float*)d_in[20], (const float*)d_in[21],
      (const float*)d_in[22], (const float*)d_in[23],
      (float*)d_out, n_poly);
}